// round 16
// baseline (speedup 1.0000x reference)
#include <cuda_runtime.h>
#include <math.h>

// Problem constants
#define BATCH   64
#define IN_D    256
#define MEM_D   128
#define NSLOT   4096
#define CPB     8                  // chunks (blocks) per batch -> single wave
#define CHUNK   (NSLOT / CPB)      // 512 rows per block
#define KQ      8                  // K slices in proj (32 each)
#define TROWS   32                 // rows per cp.async tile
#define NTILE   (CHUNK / TROWS)    // 16 tiles

// -------- scratch (no device allocations allowed) --------
__device__ float g_pp[3 * BATCH * KQ * MEM_D]; // proj partials [m][b][kq][o]
__device__ float g_rop[BATCH * CPB * MEM_D];   // per-chunk read_out partials

__device__ float g_pm1[BATCH * CPB];
__device__ float g_pz1[BATCH * CPB];
__device__ float g_pm2[BATCH * CPB];
__device__ float g_pz2[BATCH * CPB];
__device__ float g_ps2[BATCH * CPB];
__device__ int   g_cnt1[BATCH];                // zero-init; reset by epilogue
__device__ int   g_cnt2[BATCH];
__device__ int   g_cnt3[BATCH];

__device__ __forceinline__ float warpSum(float v) {
#pragma unroll
    for (int o = 16; o; o >>= 1) v += __shfl_xor_sync(0xffffffffu, v, o);
    return v;
}
__device__ __forceinline__ float warpMax(float v) {
#pragma unroll
    for (int o = 16; o; o >>= 1) v = fmaxf(v, __shfl_xor_sync(0xffffffffu, v, o));
    return v;
}
// block reduce for 256 threads (8 warps)
__device__ __forceinline__ float blockSum(float v, float* sred) {
    v = warpSum(v);
    if ((threadIdx.x & 31) == 0) sred[threadIdx.x >> 5] = v;
    __syncthreads();
    float r = sred[0];
#pragma unroll
    for (int i = 1; i < 8; i++) r += sred[i];
    __syncthreads();
    return r;
}
__device__ __forceinline__ float blockMax(float v, float* sred) {
    v = warpMax(v);
    if ((threadIdx.x & 31) == 0) sred[threadIdx.x >> 5] = v;
    __syncthreads();
    float r = sred[0];
#pragma unroll
    for (int i = 1; i < 8; i++) r = fmaxf(r, sred[i]);
    __syncthreads();
    return r;
}

__device__ __forceinline__ void cp16(float4* dst_smem, const float4* src) {
    unsigned sa = (unsigned)__cvta_generic_to_shared(dst_smem);
    asm volatile("cp.async.cg.shared.global [%0], [%1], 16;\n"
                 :: "r"(sa), "l"(src) : "memory");
}

// ---------------------------------------------------------------------------
// Kernel 1: projection PARTIALS. grid = 1536 (3 x 64 x 8 K-slices), blk 128.
// No smem, no sync: x via uniform broadcast loads, W coalesced.
// ---------------------------------------------------------------------------
__global__ void __launch_bounds__(128)
proj_kernel(const float* __restrict__ x,
            const float* __restrict__ Ww,
            const float* __restrict__ Wq,
            const float* __restrict__ Wr) {
    const int m   = blockIdx.x >> 9;          // 0..2
    const int rem = blockIdx.x & 511;
    const int b   = rem >> 3;                 // 0..63
    const int kq  = rem & 7;                  // K slice
    const int t   = threadIdx.x;              // 0..127 (output column)

    const float* W = (m == 0) ? Ww : ((m == 1) ? Wq : Wr);
    const int k0 = kq * 32;
    const float* xb = x + b * IN_D + k0;      // uniform across block
    const float* Wc = W + (size_t)k0 * MEM_D + t;

    float a0 = 0.f, a1 = 0.f, a2 = 0.f, a3 = 0.f;
#pragma unroll
    for (int k = 0; k < 32; k += 4) {
        const float x0 = __ldg(xb + k + 0);
        const float x1 = __ldg(xb + k + 1);
        const float x2 = __ldg(xb + k + 2);
        const float x3 = __ldg(xb + k + 3);
        a0 = fmaf(x0, Wc[(k + 0) * MEM_D], a0);
        a1 = fmaf(x1, Wc[(k + 1) * MEM_D], a1);
        a2 = fmaf(x2, Wc[(k + 2) * MEM_D], a2);
        a3 = fmaf(x3, Wc[(k + 3) * MEM_D], a3);
    }
    g_pp[(((m * BATCH) + b) * KQ + kq) * MEM_D + t] = (a0 + a1) + (a2 + a3);
}

// ---------------------------------------------------------------------------
// Kernel 2: FUSED dots + dual-softmax + accumulation + OUTPUT, SINGLE WAVE.
// grid = 512 (64 x 8 chunks), block 256, 4 blocks/SM -> all resident.
// BOTH memory passes are cp.async double-buffered own-slot pipelines
// (no block syncs inside the loops; deep MLP independent of registers).
// Phase 2 runs tiles in REVERSE order (L2-hot) with .cg (L1 bypass).
// Barrier 2 split (arrive before phase 2, wait after).
// Epilogue: ch==0 block reduces rop + s*v, projects through W_ro, resets cnts.
// ---------------------------------------------------------------------------
__global__ void __launch_bounds__(256, 4)
fused_kernel(const float* __restrict__ mem,
             const float* __restrict__ bw,
             const float* __restrict__ bq,
             const float* __restrict__ br,
             const float* __restrict__ Wro,
             const float* __restrict__ bro,
             float* __restrict__ out) {
    const int b  = blockIdx.x >> 3;
    const int ch = blockIdx.x & 7;
    const int bi = blockIdx.x;
    const int t  = threadIdx.x;
    const int lane = t & 31;
    const int s = lane & 7;                   // col-slice owner
    const int trow = t >> 3;                  // 0..31 tile row owner

    // 32KB pool: two 16KB cp.async tiles; pacc overlays after phase 2 reads
    __shared__ __align__(16) char pool[32768];
    float4* tile0 = (float4*)pool;                   // 1024 float4
    float4* tile1 = tile0 + TROWS * 32;              // 1024 float4
    float4* pacc  = (float4*)pool;                   // 1024 float4 (overlay)

    __shared__ float sd1[CHUNK];              // d1 -> ww -> c'
    __shared__ float sd2[CHUNK];              // d2 -> rl
    __shared__ float swq[MEM_D];
    __shared__ float srq[MEM_D];              // later reused as sr (epilogue)
    __shared__ float sv [MEM_D];
    __shared__ float sred[8];
    __shared__ float sbc[3];

    if (t < MEM_D) {
        const float* pv = g_pp + ((0 * BATCH + b) * KQ) * MEM_D + t;
        const float* pq = g_pp + ((1 * BATCH + b) * KQ) * MEM_D + t;
        const float* pr = g_pp + ((2 * BATCH + b) * KQ) * MEM_D + t;
        float av = bw[t], aq = bq[t], ar = br[t];
#pragma unroll
        for (int j = 0; j < KQ; j++) {
            av += pv[j * MEM_D];
            aq += pq[j * MEM_D];
            ar += pr[j * MEM_D];
        }
        sv[t] = av; swq[t] = aq; srq[t] = ar;
    }
    __syncthreads();

    // per-thread query slices (cols (j*8+s)*4 .. +3)
    float4 q4[4], r4[4];
#pragma unroll
    for (int j = 0; j < 4; j++) {
        q4[j] = reinterpret_cast<const float4*>(swq)[j * 8 + s];
        r4[j] = reinterpret_cast<const float4*>(srq)[j * 8 + s];
    }

    const float4* mb = reinterpret_cast<const float4*>(mem) +
                       ((size_t)b * NSLOT + (size_t)ch * CHUNK) * 32;

    // ======= Phase 1: cp.async pipelined dots (own-slot, no barriers) =======
    {
#pragma unroll
        for (int j = 0; j < 4; j++)
            cp16(tile0 + trow * 32 + j * 8 + s,
                 mb + (size_t)trow * 32 + j * 8 + s);
        asm volatile("cp.async.commit_group;" ::: "memory");
#pragma unroll
        for (int j = 0; j < 4; j++)
            cp16(tile1 + trow * 32 + j * 8 + s,
                 mb + (size_t)(TROWS + trow) * 32 + j * 8 + s);
        asm volatile("cp.async.commit_group;" ::: "memory");

        for (int it = 0; it < NTILE; it++) {
            float4* cur = (it & 1) ? tile1 : tile0;
            if (it < NTILE - 1) {
                asm volatile("cp.async.wait_group 1;" ::: "memory");
            } else {
                asm volatile("cp.async.wait_group 0;" ::: "memory");
            }
            float a = 0.0f, c = 0.0f;
#pragma unroll
            for (int j = 0; j < 4; j++) {
                const float4 m = cur[trow * 32 + j * 8 + s];
                a = fmaf(m.x, q4[j].x, a); a = fmaf(m.y, q4[j].y, a);
                a = fmaf(m.z, q4[j].z, a); a = fmaf(m.w, q4[j].w, a);
                c = fmaf(m.x, r4[j].x, c); c = fmaf(m.y, r4[j].y, c);
                c = fmaf(m.z, r4[j].z, c); c = fmaf(m.w, r4[j].w, c);
            }
#pragma unroll
            for (int o = 4; o; o >>= 1) {     // reduce over s (8 lanes)
                a += __shfl_xor_sync(0xffffffffu, a, o);
                c += __shfl_xor_sync(0xffffffffu, c, o);
            }
            if (s == 0) {
                sd1[it * TROWS + trow] = a;
                sd2[it * TROWS + trow] = c;
            }
            if (it + 2 < NTILE) {
#pragma unroll
                for (int j = 0; j < 4; j++)
                    cp16(cur + trow * 32 + j * 8 + s,
                         mb + (size_t)((it + 2) * TROWS + trow) * 32 + j * 8 + s);
                asm volatile("cp.async.commit_group;" ::: "memory");
            }
        }
    }

    // qv = v . rq  (blockSum's internal syncs also publish sd1/sd2)
    float qp = (t < MEM_D) ? sv[t] * srq[t] : 0.0f;
    __syncthreads();
    const float qv = blockSum(qp, sred);

    // ---- local write-softmax partials (2 elems per thread) ----
    const float m1 = blockMax(fmaxf(sd1[t], sd1[t + 256]), sred);
    const float z1 = blockSum(__expf(sd1[t] - m1) + __expf(sd1[t + 256] - m1),
                              sred);

    // ---- barrier 1: full wait (ww needs global M1/Z1) ----
    if (t == 0) {
        *(volatile float*)&g_pm1[bi] = m1;
        *(volatile float*)&g_pz1[bi] = z1;
        __threadfence();
        atomicAdd(&g_cnt1[b], 1);
        while (atomicAdd(&g_cnt1[b], 0) < CPB) __nanosleep(32);
        __threadfence();
    }
    __syncthreads();
    if (t < 32) {
        const float pm = (t < CPB) ? *(volatile float*)&g_pm1[b * CPB + t] : -1e30f;
        const float pz = (t < CPB) ? *(volatile float*)&g_pz1[b * CPB + t] : 0.0f;
        const float M  = warpMax(pm);
        const float Z  = warpSum(pz * __expf(pm - M));
        if (t == 0) { sbc[0] = M; sbc[1] = 1.0f / Z; }
    }
    __syncthreads();
    const float M1 = sbc[0], invZ1 = sbc[1];

    // ---- ww (exact), read-logits; local read-softmax partials ----
    float m2l = -1e30f;
#pragma unroll
    for (int i = 0; i < 2; i++) {
        const int n = t + i * 256;
        const float ww = __expf(sd1[n] - M1) * invZ1;
        const float d2v = sd2[n];
        const float rl = d2v - ww * (d2v - qv);
        sd1[n] = ww;
        sd2[n] = rl;
        m2l = fmaxf(m2l, rl);
    }
    const float m2 = blockMax(m2l, sred);
    float lz2 = 0.0f, ls2 = 0.0f;
#pragma unroll
    for (int i = 0; i < 2; i++) {
        const int n = t + i * 256;
        const float e = __expf(sd2[n] - m2);
        lz2 += e;
        ls2 += e * sd1[n];
    }
    const float z2 = blockSum(lz2, sred);
    const float s2 = blockSum(ls2, sred);

    // ---- barrier 2: ARRIVE ONLY (wait deferred past phase 2) ----
    if (t == 0) {
        *(volatile float*)&g_pm2[bi] = m2;
        *(volatile float*)&g_pz2[bi] = z2;
        *(volatile float*)&g_ps2[bi] = s2;
        __threadfence();
        atomicAdd(&g_cnt2[b], 1);
    }

    // ---- c'_n = e^{rl_n - m2_loc} * (1 - ww_n)  (locally-scaled coeff) ----
#pragma unroll
    for (int i = 0; i < 2; i++) {
        const int n = t + i * 256;
        sd1[n] = __expf(sd2[n] - m2) * (1.0f - sd1[n]);
    }
    __syncthreads();

    // ======= Phase 2: cp.async pipelined weighted sum, REVERSE order =======
    float4 acc[4];
#pragma unroll
    for (int j = 0; j < 4; j++) acc[j] = make_float4(0.f, 0.f, 0.f, 0.f);
    {
        // prologue: tiles NTILE-1, NTILE-2 in flight
#pragma unroll
        for (int j = 0; j < 4; j++)
            cp16(tile0 + trow * 32 + j * 8 + s,
                 mb + (size_t)((NTILE - 1) * TROWS + trow) * 32 + j * 8 + s);
        asm volatile("cp.async.commit_group;" ::: "memory");
#pragma unroll
        for (int j = 0; j < 4; j++)
            cp16(tile1 + trow * 32 + j * 8 + s,
                 mb + (size_t)((NTILE - 2) * TROWS + trow) * 32 + j * 8 + s);
        asm volatile("cp.async.commit_group;" ::: "memory");

        for (int k = 0; k < NTILE; k++) {      // k-th tile = NTILE-1-k
            float4* cur = (k & 1) ? tile1 : tile0;
            if (k < NTILE - 1) {
                asm volatile("cp.async.wait_group 1;" ::: "memory");
            } else {
                asm volatile("cp.async.wait_group 0;" ::: "memory");
            }
            const int row = (NTILE - 1 - k) * TROWS + trow;
            const float cv = sd1[row];
#pragma unroll
            for (int j = 0; j < 4; j++) {
                const float4 m = cur[trow * 32 + j * 8 + s];
                acc[j].x = fmaf(cv, m.x, acc[j].x);
                acc[j].y = fmaf(cv, m.y, acc[j].y);
                acc[j].z = fmaf(cv, m.z, acc[j].z);
                acc[j].w = fmaf(cv, m.w, acc[j].w);
            }
            if (k + 2 < NTILE) {
#pragma unroll
                for (int j = 0; j < 4; j++)
                    cp16(cur + trow * 32 + j * 8 + s,
                         mb + (size_t)((NTILE - 3 - k) * TROWS + trow) * 32
                            + j * 8 + s);
                asm volatile("cp.async.commit_group;" ::: "memory");
            }
        }
    }
    __syncthreads();                          // all tile reads done -> free pool
    // store per-thread partials: pacc[t*4+j] covers cols (j*8+s)*4..+3, trow
#pragma unroll
    for (int j = 0; j < 4; j++) pacc[t * 4 + j] = acc[j];

    // ---- barrier 2: WAIT + combine (overlapped with peers' phase 2) ----
    if (t == 0) {
        while (atomicAdd(&g_cnt2[b], 0) < CPB) __nanosleep(32);
        __threadfence();
    }
    __syncthreads();
    if (t < 32) {
        const float pm = (t < CPB) ? *(volatile float*)&g_pm2[b * CPB + t] : -1e30f;
        const float pz = (t < CPB) ? *(volatile float*)&g_pz2[b * CPB + t] : 0.0f;
        const float ps = (t < CPB) ? *(volatile float*)&g_ps2[b * CPB + t] : 0.0f;
        const float M  = warpMax(pm);
        const float e  = __expf(pm - M);
        const float Z  = warpSum(pz * e);
        const float S  = warpSum(ps * e);
        if (t == 0) { sbc[0] = M; sbc[1] = 1.0f / Z; sbc[2] = S / Z; }
    }
    __syncthreads();
    const float scale = __expf(m2 - sbc[0]) * sbc[1];   // e^{m2-M2}/Z2
    const float sval  = sbc[2];                          // s_b

    // reduce pacc over the 32 trow groups; thread cf<32 owns col-float4 cf
    if (t < 32) {
        const int js = t;                     // cf = j*8+s  ->  j=t>>3, s=t&7
        const int jj = js >> 3, ss = js & 7;
        float4 ssum = make_float4(0.f, 0.f, 0.f, 0.f);
#pragma unroll 8
        for (int r = 0; r < 32; r++) {
            const float4 u = pacc[(r * 8 + ss) * 4 + jj];
            ssum.x += u.x; ssum.y += u.y; ssum.z += u.z; ssum.w += u.w;
        }
        ssum.x *= scale; ssum.y *= scale; ssum.z *= scale; ssum.w *= scale;
        reinterpret_cast<float4*>(g_rop + (size_t)bi * MEM_D)[js] = ssum;
    }
    __syncthreads();                          // rop stores issued
    if (t == 0) {
        __threadfence();
        atomicAdd(&g_cnt3[b], 1);
    }

    // ============ Epilogue: ch==0 block finishes the batch ============
    if (ch != 0) return;
    if (t == 0) {
        while (atomicAdd(&g_cnt3[b], 0) < CPB) __nanosleep(32);
        __threadfence();
    }
    __syncthreads();

    // sr (reuse srq) = sum_ch rop + s * v
    if (t < MEM_D) {
        float accr = sval * sv[t];
        const float* rp = g_rop + (size_t)b * CPB * MEM_D + t;
#pragma unroll
        for (int c = 0; c < CPB; c++) accr += __ldcg(rp + c * MEM_D);
        srq[t] = accr;
    }
    if (t == 0) {                             // reset counters for next replay
        g_cnt1[b] = 0; g_cnt2[b] = 0; g_cnt3[b] = 0;
    }
    __syncthreads();

    // out[b, t] = bro[t] + sum_d sr[d] * Wro[d*IN_D + t]   (256 threads)
    {
        float a0 = 0.f, a1 = 0.f;
#pragma unroll 8
        for (int d = 0; d < MEM_D; d += 2) {
            a0 = fmaf(srq[d],     Wro[(d)     * IN_D + t], a0);
            a1 = fmaf(srq[d + 1], Wro[(d + 1) * IN_D + t], a1);
        }
        out[b * IN_D + t] = a0 + a1 + bro[t];
    }
}

// ---------------------------------------------------------------------------
extern "C" void kernel_launch(void* const* d_in, const int* in_sizes, int n_in,
                              void* d_out, int out_size) {
    const float* x   = (const float*)d_in[0];
    const float* mem = (const float*)d_in[1];
    const float* Ww  = (const float*)d_in[2];
    const float* bw  = (const float*)d_in[3];
    const float* Wq  = (const float*)d_in[4];
    const float* bq  = (const float*)d_in[5];
    const float* Wr  = (const float*)d_in[6];
    const float* br  = (const float*)d_in[7];
    const float* Wro = (const float*)d_in[8];
    const float* bro = (const float*)d_in[9];
    float* out = (float*)d_out;

    proj_kernel<<<3 * BATCH * KQ, 128>>>(x, Ww, Wq, Wr);
    fused_kernel<<<BATCH * CPB, 256>>>(mem, bw, bq, br, Wro, bro, out);
}